// round 6
// baseline (speedup 1.0000x reference)
#include <cuda_runtime.h>
#include <cstdint>

#define Bn   4096
#define Tn   64
#define DIN  300
#define Hn   3
#define DIN4 75      // 300/4
#define C2LE 2.885390081777927f   // 2*log2(e): folded into xb and W_hh

// xb in padded [t][b][4] layout, PRE-SCALED by 2*log2(e).
__device__ float g_xb[(size_t)Tn * Bn * 4];   // 4 MB

// lengths may arrive as int32 or int64. Values in [1,64] so for int64 the
// high word of element 0 — ((int*)L)[1] — is 0; for int32 it is lengths[1]>=1.
__device__ __forceinline__ int detect_is64(const void* L) {
    return ((const int*)L)[1] == 0;
}
__device__ __forceinline__ int length_at(const void* L, int b, int is64) {
    if (is64) return (int)((const long long*)L)[b];
    return ((const int*)L)[b];
}

__device__ __forceinline__ uint32_t smem_u32(const void* p) {
    uint32_t a;
    asm("{ .reg .u64 t; cvta.to.shared.u64 t, %1; cvt.u32.u64 %0, t; }"
        : "=r"(a) : "l"(p));
    return a;
}

// tanh from pre-scaled argument a = 2*log2(e)*x:
//   tanh(x) = 1 - 2/(2^a + 1).  MUFU EX2 + MUFU RCP, few-ulp, saturates right.
__device__ __forceinline__ float tanh_pre(float a) {
    float e, r;
    asm("ex2.approx.f32 %0, %1;" : "=f"(e) : "f"(a));
    asm("rcp.approx.f32 %0, %1;" : "=f"(r) : "f"(e + 1.0f));
    return fmaf(-2.0f, r, 1.0f);
}

// ---------------------------------------------------------------------------
// Phase 1: xb[t][b][.] = (x[b,t,:].W_ih[h,:] + b_ih[h] + b_hh[h]) * 2log2e
// One warp = 8 consecutive timesteps of one sample, processed as a BATCH:
// 24 accumulators, loads for all 8 rows issued per k-slice (high MLP),
// all 8 shfl-reduction chains at the end (pipelined, independent).
// Weights in 9 float4 registers per lane -> inner loop is LDG.128 + FMA only.
// ---------------------------------------------------------------------------
__global__ __launch_bounds__(256) void k_proj(
    const float* __restrict__ x,
    const void*  __restrict__ L,
    const float* __restrict__ W_ih,
    const float* __restrict__ b_ih,
    const float* __restrict__ b_hh)
{
    const int gw   = (blockIdx.x * blockDim.x + threadIdx.x) >> 5;
    const int lane = threadIdx.x & 31;
    const int b     = gw >> 3;
    const int tbase = (gw & 7) << 3;

    const int is64 = detect_is64(L);
    const int len  = length_at(L, b, is64);
    if (tbase >= len) return;                      // dead: zero HBM traffic
    const int nrows = (len - tbase < 8) ? (len - tbase) : 8;

    // per-lane weight slices: w[h][k] covers cols 4*(lane+32k)..+3
    const float4* __restrict__ W4 = (const float4*)W_ih;
    float4 w[Hn][3];
    #pragma unroll
    for (int h = 0; h < Hn; ++h)
        #pragma unroll
        for (int k = 0; k < 3; ++k) {
            const int j = lane + 32 * k;
            w[h][k] = (j < DIN4) ? W4[h * DIN4 + j] : make_float4(0.f,0.f,0.f,0.f);
        }

    const float bs0 = b_ih[0] + b_hh[0];
    const float bs1 = b_ih[1] + b_hh[1];
    const float bs2 = b_ih[2] + b_hh[2];

    const float4* __restrict__ xr = (const float4*)x + (size_t)(b * Tn + tbase) * DIN4;

    float acc[8][3];
    #pragma unroll
    for (int r = 0; r < 8; ++r) { acc[r][0]=0.f; acc[r][1]=0.f; acc[r][2]=0.f; }

    #pragma unroll
    for (int k = 0; k < 3; ++k) {
        const int j = lane + 32 * k;
        const bool pr = (j < DIN4);
        float4 v[8];
        #pragma unroll
        for (int r = 0; r < 8; ++r)
            v[r] = (pr && r < nrows) ? xr[r * DIN4 + j] : make_float4(0.f,0.f,0.f,0.f);
        #pragma unroll
        for (int r = 0; r < 8; ++r) {
            acc[r][0] += v[r].x*w[0][k].x + v[r].y*w[0][k].y + v[r].z*w[0][k].z + v[r].w*w[0][k].w;
            acc[r][1] += v[r].x*w[1][k].x + v[r].y*w[1][k].y + v[r].z*w[1][k].z + v[r].w*w[1][k].w;
            acc[r][2] += v[r].x*w[2][k].x + v[r].y*w[2][k].y + v[r].z*w[2][k].z + v[r].w*w[2][k].w;
        }
    }

    // 8 independent butterfly reductions -> chains overlap
    #pragma unroll
    for (int r = 0; r < 8; ++r) {
        #pragma unroll
        for (int off = 16; off; off >>= 1) {
            acc[r][0] += __shfl_xor_sync(0xffffffffu, acc[r][0], off);
            acc[r][1] += __shfl_xor_sync(0xffffffffu, acc[r][1], off);
            acc[r][2] += __shfl_xor_sync(0xffffffffu, acc[r][2], off);
        }
    }

    float4* __restrict__ xb4 = (float4*)g_xb;
    #pragma unroll
    for (int r = 0; r < 8; ++r) {
        if (r < nrows && lane == 0) {
            float4 o;
            o.x = (acc[r][0] + bs0) * C2LE;
            o.y = (acc[r][1] + bs1) * C2LE;
            o.z = (acc[r][2] + bs2) * C2LE;
            o.w = 0.f;
            xb4[(size_t)(tbase + r) * Bn + b] = o;
        }
    }
}

// ---------------------------------------------------------------------------
// Phase 2: sequential recurrence, one thread per sample. g_xb was evicted to
// DRAM by the 314MB x stream, so stage the whole trajectory into shared memory
// with cp.async (predicated on t < len; 4 commit groups, incremental waits),
// then run the chain out of smem with 1-ahead prefetch. W_hh pre-scaled by
// 2log2e to match the pre-scaled xb; tanh = 1 - 2*rcp(ex2(a)+1).
// ---------------------------------------------------------------------------
__global__ __launch_bounds__(32) void k_rnn(
    const void*  __restrict__ L,
    const float* __restrict__ W_hh,
    float*       __restrict__ out)
{
    __shared__ float4 buf[Tn][32];     // 32 KB
    const int tid = threadIdx.x;
    const int b   = blockIdx.x * 32 + tid;
    const int is64 = detect_is64(L);
    const int len  = length_at(L, b, is64);   // >= 1

    const float4* __restrict__ p = (const float4*)g_xb;

    // issue 4 groups of 16 staged copies (only live steps)
    #pragma unroll
    for (int g = 0; g < 4; ++g) {
        #pragma unroll
        for (int tl = 0; tl < 16; ++tl) {
            const int t = g * 16 + tl;
            if (t < len) {
                const uint32_t d = smem_u32(&buf[t][tid]);
                const float4* s = p + (size_t)t * Bn + b;
                asm volatile("cp.async.cg.shared.global [%0], [%1], 16;"
                             :: "r"(d), "l"(s) : "memory");
            }
        }
        asm volatile("cp.async.commit_group;" ::: "memory");
    }

    const float w00 = W_hh[0]*C2LE, w01 = W_hh[1]*C2LE, w02 = W_hh[2]*C2LE;
    const float w10 = W_hh[3]*C2LE, w11 = W_hh[4]*C2LE, w12 = W_hh[5]*C2LE;
    const float w20 = W_hh[6]*C2LE, w21 = W_hh[7]*C2LE, w22 = W_hh[8]*C2LE;

    float h0 = 0.f, h1 = 0.f, h2 = 0.f;

    #define RNN_CHUNK(G, WAITN)                                               \
    if (len > (G) * 16) {                                                     \
        asm volatile("cp.async.wait_group " #WAITN ";" ::: "memory");         \
        const int e = (len - (G)*16 < 16) ? (len - (G)*16) : 16;              \
        float4 cur = buf[(G)*16][tid];                                        \
        for (int tl = 0; tl < e; ++tl) {                                      \
            float4 nxt = (tl + 1 < e) ? buf[(G)*16 + tl + 1][tid] : cur;      \
            const float a0 = cur.x + h0*w00 + h1*w01 + h2*w02;                \
            const float a1 = cur.y + h0*w10 + h1*w11 + h2*w12;                \
            const float a2 = cur.z + h0*w20 + h1*w21 + h2*w22;                \
            h0 = tanh_pre(a0);                                                \
            h1 = tanh_pre(a1);                                                \
            h2 = tanh_pre(a2);                                                \
            cur = nxt;                                                        \
        }                                                                     \
    }

    RNN_CHUNK(0, 3)
    RNN_CHUNK(1, 2)
    RNN_CHUNK(2, 1)
    RNN_CHUNK(3, 0)
    #undef RNN_CHUNK

    out[b * Hn + 0] = h0;
    out[b * Hn + 1] = h1;
    out[b * Hn + 2] = h2;
}

extern "C" void kernel_launch(void* const* d_in, const int* in_sizes, int n_in,
                              void* d_out, int out_size)
{
    const float* x    = (const float*)d_in[0];
    const void*  L    = d_in[1];
    const float* W_ih = (const float*)d_in[2];
    const float* W_hh = (const float*)d_in[3];
    const float* b_ih = (const float*)d_in[4];
    const float* b_hh = (const float*)d_in[5];
    float* out = (float*)d_out;

    k_proj<<<4096, 256>>>(x, L, W_ih, b_ih, b_hh);
    k_rnn<<<Bn / 32, 32>>>(L, W_hh, out);
}

// round 8
// speedup vs baseline: 1.2214x; 1.2214x over previous
#include <cuda_runtime.h>
#include <cstdint>

#define Bn   4096
#define Tn   64
#define DIN  300
#define Hn   3
#define DIN4 75      // 300/4
#define C2LE 2.885390081777927f   // 2*log2(e): folded into xb and W_hh

// xb in padded [t][b][4] layout, PRE-SCALED by 2*log2(e).
__device__ float g_xb[(size_t)Tn * Bn * 4];   // 4 MB

// lengths may arrive as int32 or int64. Values in [1,64] so for int64 the
// high word of element 0 — ((int*)L)[1] — is 0; for int32 it is lengths[1]>=1.
__device__ __forceinline__ int detect_is64(const void* L) {
    return ((const int*)L)[1] == 0;
}
__device__ __forceinline__ int length_at(const void* L, int b, int is64) {
    if (is64) return (int)((const long long*)L)[b];
    return ((const int*)L)[b];
}

__device__ __forceinline__ uint32_t smem_u32(const void* p) {
    uint32_t a;
    asm("{ .reg .u64 t; cvta.to.shared.u64 t, %1; cvt.u32.u64 %0, t; }"
        : "=r"(a) : "l"(p));
    return a;
}

// tanh from pre-scaled argument a = 2*log2(e)*x:
//   tanh(x) = 1 - 2/(2^a + 1).  MUFU EX2 + MUFU RCP, few-ulp, saturates right.
__device__ __forceinline__ float tanh_pre(float a) {
    float e, r;
    asm("ex2.approx.f32 %0, %1;" : "=f"(e) : "f"(a));
    asm("rcp.approx.f32 %0, %1;" : "=f"(r) : "f"(e + 1.0f));
    return fmaf(-2.0f, r, 1.0f);
}

// ---------------------------------------------------------------------------
// Phase 1: xb[t][b][.] = (x[b,t,:].W_ih[h,:] + b_ih[h] + b_hh[h]) * 2log2e
// One warp = NR (<=4) consecutive timesteps of one sample. Two-wave load
// pipeline keeps 2*NR LDG.128 in flight while FMAs consume the previous wave;
// weights live in 9 float4 regs/lane; NR shfl-reduction chains pipelined.
// ---------------------------------------------------------------------------
template<int NR>
__device__ __forceinline__ void proj_rows(
    const float4* __restrict__ xr,      // row 0 of this group
    const float4 (&w)[Hn][3], int lane,
    float bs0, float bs1, float bs2,
    float4* __restrict__ xb4, int tbase, int b)
{
    const int j0 = lane;
    const int j1 = lane + 32;
    const int j2 = lane + 64;
    const bool p2 = (j2 < DIN4);        // only wave 2 is partial

    float acc[NR][3];
    #pragma unroll
    for (int r = 0; r < NR; ++r) { acc[r][0]=0.f; acc[r][1]=0.f; acc[r][2]=0.f; }

    float4 v0[NR], v1[NR];
    #pragma unroll
    for (int r = 0; r < NR; ++r) v0[r] = xr[r * DIN4 + j0];          // wave 0
    #pragma unroll
    for (int r = 0; r < NR; ++r) v1[r] = xr[r * DIN4 + j1];          // wave 1

    #pragma unroll
    for (int r = 0; r < NR; ++r) {                                    // fma wave 0
        #pragma unroll
        for (int h = 0; h < Hn; ++h)
            acc[r][h] += v0[r].x*w[h][0].x + v0[r].y*w[h][0].y
                       + v0[r].z*w[h][0].z + v0[r].w*w[h][0].w;
    }
    #pragma unroll
    for (int r = 0; r < NR; ++r)                                      // wave 2
        v0[r] = p2 ? xr[r * DIN4 + j2] : make_float4(0.f,0.f,0.f,0.f);
    #pragma unroll
    for (int r = 0; r < NR; ++r) {                                    // fma wave 1
        #pragma unroll
        for (int h = 0; h < Hn; ++h)
            acc[r][h] += v1[r].x*w[h][1].x + v1[r].y*w[h][1].y
                       + v1[r].z*w[h][1].z + v1[r].w*w[h][1].w;
    }
    #pragma unroll
    for (int r = 0; r < NR; ++r) {                                    // fma wave 2
        #pragma unroll
        for (int h = 0; h < Hn; ++h)
            acc[r][h] += v0[r].x*w[h][2].x + v0[r].y*w[h][2].y
                       + v0[r].z*w[h][2].z + v0[r].w*w[h][2].w;
    }

    // NR independent butterfly reductions (chains overlap)
    #pragma unroll
    for (int r = 0; r < NR; ++r) {
        #pragma unroll
        for (int off = 16; off; off >>= 1) {
            acc[r][0] += __shfl_xor_sync(0xffffffffu, acc[r][0], off);
            acc[r][1] += __shfl_xor_sync(0xffffffffu, acc[r][1], off);
            acc[r][2] += __shfl_xor_sync(0xffffffffu, acc[r][2], off);
        }
    }

    if (lane == 0) {
        #pragma unroll
        for (int r = 0; r < NR; ++r) {
            float4 o;
            o.x = (acc[r][0] + bs0) * C2LE;
            o.y = (acc[r][1] + bs1) * C2LE;
            o.z = (acc[r][2] + bs2) * C2LE;
            o.w = 0.f;
            xb4[(size_t)(tbase + r) * Bn + b] = o;
        }
    }
}

__global__ __launch_bounds__(256) void k_proj(
    const float* __restrict__ x,
    const void*  __restrict__ L,
    const float* __restrict__ W_ih,
    const float* __restrict__ b_ih,
    const float* __restrict__ b_hh)
{
    const int gw   = (blockIdx.x * blockDim.x + threadIdx.x) >> 5;
    const int lane = threadIdx.x & 31;
    const int b     = gw >> 4;          // 16 groups of 4 rows per sample
    const int tbase = (gw & 15) << 2;

    const int is64 = detect_is64(L);
    const int len  = length_at(L, b, is64);
    if (tbase >= len) return;           // dead: zero HBM traffic
    const int nrows = (len - tbase < 4) ? (len - tbase) : 4;

    // per-lane weight slices: w[h][k] covers cols 4*(lane+32k)..+3
    const float4* __restrict__ W4 = (const float4*)W_ih;
    float4 w[Hn][3];
    #pragma unroll
    for (int h = 0; h < Hn; ++h)
        #pragma unroll
        for (int k = 0; k < 3; ++k) {
            const int j = lane + 32 * k;
            w[h][k] = (j < DIN4) ? W4[h * DIN4 + j] : make_float4(0.f,0.f,0.f,0.f);
        }

    const float bs0 = b_ih[0] + b_hh[0];
    const float bs1 = b_ih[1] + b_hh[1];
    const float bs2 = b_ih[2] + b_hh[2];

    const float4* __restrict__ xr = (const float4*)x + (size_t)(b * Tn + tbase) * DIN4;
    float4* __restrict__ xb4 = (float4*)g_xb;

    switch (nrows) {
        case 4: proj_rows<4>(xr, w, lane, bs0, bs1, bs2, xb4, tbase, b); break;
        case 3: proj_rows<3>(xr, w, lane, bs0, bs1, bs2, xb4, tbase, b); break;
        case 2: proj_rows<2>(xr, w, lane, bs0, bs1, bs2, xb4, tbase, b); break;
        default: proj_rows<1>(xr, w, lane, bs0, bs1, bs2, xb4, tbase, b); break;
    }
}

// ---------------------------------------------------------------------------
// Phase 2: branchless sequential recurrence, one thread per sample.
// cp.async stages ALL 64 steps (unguarded -> no divergence; dead entries are
// discarded by the freeze-select, never propagate). Fully unrolled 64 steps,
// FSEL freeze mask, 2-ahead smem prefetch, compile-time wait boundaries.
// ---------------------------------------------------------------------------
__global__ __launch_bounds__(32) void k_rnn(
    const void*  __restrict__ L,
    const float* __restrict__ W_hh,
    float*       __restrict__ out)
{
    __shared__ float4 buf[Tn][32];     // 32 KB
    const int tid = threadIdx.x;
    const int b   = blockIdx.x * 32 + tid;
    const int is64 = detect_is64(L);
    const int len  = length_at(L, b, is64);   // >= 1

    const float4* __restrict__ p = (const float4*)g_xb;

    // stage whole trajectory: 4 commit groups of 16 steps, unguarded
    #pragma unroll
    for (int g = 0; g < 4; ++g) {
        #pragma unroll
        for (int tl = 0; tl < 16; ++tl) {
            const int t = g * 16 + tl;
            const uint32_t d = smem_u32(&buf[t][tid]);
            const float4* s = p + (size_t)t * Bn + b;
            asm volatile("cp.async.cg.shared.global [%0], [%1], 16;"
                         :: "r"(d), "l"(s) : "memory");
        }
        asm volatile("cp.async.commit_group;" ::: "memory");
    }

    const float w00 = W_hh[0]*C2LE, w01 = W_hh[1]*C2LE, w02 = W_hh[2]*C2LE;
    const float w10 = W_hh[3]*C2LE, w11 = W_hh[4]*C2LE, w12 = W_hh[5]*C2LE;
    const float w20 = W_hh[6]*C2LE, w21 = W_hh[7]*C2LE, w22 = W_hh[8]*C2LE;

    float h0 = 0.f, h1 = 0.f, h2 = 0.f;

    asm volatile("cp.async.wait_group 3;" ::: "memory");
    float4 cur = buf[0][tid];
    float4 nxt = buf[1][tid];

    #define STEP(T) do {                                                      \
        const float x0 = cur.x, x1 = cur.y, x2 = cur.z;                       \
        cur = nxt;                                                            \
        if ((T) + 2 < Tn) nxt = buf[(T) + 2][tid];                            \
        const float a0 = x0 + h0*w00 + h1*w01 + h2*w02;                       \
        const float a1 = x1 + h0*w10 + h1*w11 + h2*w12;                       \
        const float a2 = x2 + h0*w20 + h1*w21 + h2*w22;                       \
        const float t0 = tanh_pre(a0);                                        \
        const float t1 = tanh_pre(a1);                                        \
        const float t2 = tanh_pre(a2);                                        \
        const bool lv = (T) < len;                                            \
        h0 = lv ? t0 : h0;                                                    \
        h1 = lv ? t1 : h1;                                                    \
        h2 = lv ? t2 : h2;                                                    \
    } while (0)
    #define S2(T)  STEP(T); STEP((T)+1)
    #define S8(T)  S2(T); S2((T)+2); S2((T)+4); S2((T)+6)

    // STEP(T) prefetches index T+2: group1 (idx>=16) first touched at STEP(14),
    // group2 at STEP(30), group3 at STEP(46) -> waits before those steps.
    S8(0); S2(8); S2(10); S2(12);
    asm volatile("cp.async.wait_group 2;" ::: "memory");
    S2(14); S8(16); S2(24); S2(26); S2(28);
    asm volatile("cp.async.wait_group 1;" ::: "memory");
    S2(30); S8(32); S2(40); S2(42); S2(44);
    asm volatile("cp.async.wait_group 0;" ::: "memory");
    S2(46); S8(48); S8(56);

    #undef S8
    #undef S2
    #undef STEP

    out[b * Hn + 0] = h0;
    out[b * Hn + 1] = h1;
    out[b * Hn + 2] = h2;
}

extern "C" void kernel_launch(void* const* d_in, const int* in_sizes, int n_in,
                              void* d_out, int out_size)
{
    const float* x    = (const float*)d_in[0];
    const void*  L    = d_in[1];
    const float* W_ih = (const float*)d_in[2];
    const float* W_hh = (const float*)d_in[3];
    const float* b_ih = (const float*)d_in[4];
    const float* b_hh = (const float*)d_in[5];
    float* out = (float*)d_out;

    // 65536 warps (4 timesteps each), 8 warps/block -> 8192 blocks
    k_proj<<<8192, 256>>>(x, L, W_ih, b_ih, b_hh);
    k_rnn<<<Bn / 32, 32>>>(L, W_hh, out);
}